// round 14
// baseline (speedup 1.0000x reference)
#include <cuda_runtime.h>

// ---------------------------------------------------------------------------
// CombinedGoalObsNetwork — R13: R11 edge kernels (at LTS byte roofline,
// frozen) + MLP layers with L1-resident W (no SMEM, no syncthreads),
// 2 rows x 8 cols/thread, 4096 warps, x-prefetch d=1.
// ---------------------------------------------------------------------------

#define F64 64
#define NTASK_MAX  32768
#define NACT_MAX   32768

__device__ __align__(16) float g_h_task[NTASK_MAX * F64];
__device__ __align__(16) float g_tmp   [NTASK_MAX * F64];
__device__ __align__(16) float g_x1    [NTASK_MAX * F64];
__device__ __align__(16) float g_h2    [NACT_MAX  * F64];

// ---------------------------------------------------------------------------
// Init: h_task = x_task ; h2 = x_actor
// ---------------------------------------------------------------------------
__global__ void init_kernel(const float* __restrict__ x_task,
                            const float* __restrict__ x_actor,
                            int n_task, int n_actor)
{
    int tot = gridDim.x * blockDim.x;
    int tid = blockIdx.x * blockDim.x + threadIdx.x;
    int nt4 = n_task * (F64 / 4);
    int na4 = n_actor * (F64 / 4);
    const float4* xt = (const float4*)x_task;
    const float4* xa = (const float4*)x_actor;
    float4* ht = (float4*)g_h_task;
    float4* h2 = (float4*)g_h2;
    for (int i = tid; i < nt4; i += tot) ht[i] = xt[i];
    for (int i = tid; i < na4; i += tot) h2[i] = xa[i];
}

__device__ __forceinline__ void red_add_v4(float* p, float4 v)
{
    asm volatile("red.global.add.v4.f32 [%0], {%1,%2,%3,%4};"
                 :: "l"(p), "f"(v.x), "f"(v.y), "f"(v.z), "f"(v.w)
                 : "memory");
}

// ---------------------------------------------------------------------------
// GINEConv edge kernel (R11, frozen): 16 lanes/edge, float4 per lane.
// ---------------------------------------------------------------------------
__global__ void edge_gine_kernel(const float* __restrict__ x_state,
                                 const float* __restrict__ edge_attr,
                                 const float* __restrict__ We,
                                 const float* __restrict__ be,
                                 const int*   __restrict__ src,
                                 const int*   __restrict__ dst,
                                 int E)
{
    const int lane = threadIdx.x & 15;
    const float4 w0 = __ldg((const float4*)We + lane);
    const float4 w1 = __ldg((const float4*)(We + F64) + lane);
    const float4 bb = __ldg((const float4*)be + lane);

    int g  = (blockIdx.x * blockDim.x + threadIdx.x) >> 4;
    int gs = (gridDim.x * blockDim.x) >> 4;

    #pragma unroll 2
    for (int e = g; e < E; e += gs) {
        const int s = __ldg(src + e);
        const int d = __ldg(dst + e);
        const float2 a = __ldg((const float2*)edge_attr + e);
        const float4 x = __ldg((const float4*)(x_state + (size_t)s * F64) + lane);
        float4 v;
        v.x = fmaxf(fmaf(a.x, w0.x, fmaf(a.y, w1.x, x.x + bb.x)), 0.f);
        v.y = fmaxf(fmaf(a.x, w0.y, fmaf(a.y, w1.y, x.y + bb.y)), 0.f);
        v.z = fmaxf(fmaf(a.x, w0.z, fmaf(a.y, w1.z, x.z + bb.z)), 0.f);
        v.w = fmaxf(fmaf(a.x, w0.w, fmaf(a.y, w1.w, x.w + bb.w)), 0.f);
        red_add_v4(g_h_task + (size_t)d * F64 + lane * 4, v);
    }
}

// ---------------------------------------------------------------------------
// GINConv edge kernel (R11, frozen): gather x1 row, scatter-add.
// ---------------------------------------------------------------------------
__global__ void edge_gin_kernel(const int* __restrict__ src,
                                const int* __restrict__ dst,
                                int E)
{
    const int lane = threadIdx.x & 15;
    int g  = (blockIdx.x * blockDim.x + threadIdx.x) >> 4;
    int gs = (gridDim.x * blockDim.x) >> 4;

    #pragma unroll 2
    for (int e = g; e < E; e += gs) {
        const int s = __ldg(src + e);
        const int d = __ldg(dst + e);
        const float4 v = *((const float4*)(g_x1 + (size_t)s * F64) + lane);
        red_add_v4(g_h2 + (size_t)d * F64 + lane * 4, v);
    }
}

#define FMA4(acc, xk, wv4)                 \
    (acc)[0] = fmaf(xk, wv4.x, (acc)[0]);  \
    (acc)[1] = fmaf(xk, wv4.y, (acc)[1]);  \
    (acc)[2] = fmaf(xk, wv4.z, (acc)[2]);  \
    (acc)[3] = fmaf(xk, wv4.w, (acc)[3]);

// ---------------------------------------------------------------------------
// Dense 64x64 layer, L1-resident W. Block = 256 threads / 64 rows.
// Thread (rp = t>>3 in 0..31, o = t&7): rows rp, rp+32 ; cols [8o, 8o+8).
// W read via __ldg from the original row-major matrix (16KB, L1-resident;
// octant o reads W[k*64 + 8o .. +8) -> one 128B line per k, quad-broadcast).
// x prefetched one k4 step ahead. No SMEM, no __syncthreads.
// ---------------------------------------------------------------------------
__global__ void mlp_layer_kernel(const float* __restrict__ in,
                                 const float* __restrict__ W,
                                 const float* __restrict__ b,
                                 float* __restrict__ out,
                                 int n, int do_relu)
{
    const int t  = threadIdx.x;
    const int o  = t & 7;
    const int rp = t >> 3;                 // 0..31
    const int row_base = blockIdx.x * 64;
    int gr0 = row_base + rp;
    int gr1 = row_base + rp + 32;
    const bool v0 = (gr0 < n), v1 = (gr1 < n);
    if (!v0) gr0 = n - 1;
    if (!v1) gr1 = n - 1;

    const float4* x0p = (const float4*)(in + (size_t)gr0 * F64);
    const float4* x1p = (const float4*)(in + (size_t)gr1 * F64);
    const float4* wp  = (const float4*)(W + o * 8);   // row k: wp + k*16, +1

    float a0[8], a1[8];
    {
        const float4 bA = __ldg((const float4*)(b + o * 8));
        const float4 bB = __ldg((const float4*)(b + o * 8) + 1);
        a0[0]=bA.x; a0[1]=bA.y; a0[2]=bA.z; a0[3]=bA.w;
        a0[4]=bB.x; a0[5]=bB.y; a0[6]=bB.z; a0[7]=bB.w;
        #pragma unroll
        for (int j = 0; j < 8; j++) a1[j] = a0[j];
    }

    float4 c0 = __ldg(x0p);
    float4 c1 = __ldg(x1p);

    #pragma unroll
    for (int k4 = 0; k4 < 16; k4++) {
        float4 n0, n1;
        if (k4 < 15) {
            n0 = __ldg(x0p + k4 + 1);
            n1 = __ldg(x1p + k4 + 1);
        }
        #pragma unroll
        for (int kk = 0; kk < 4; kk++) {
            const float f0 = (kk==0)?c0.x:(kk==1)?c0.y:(kk==2)?c0.z:c0.w;
            const float f1 = (kk==0)?c1.x:(kk==1)?c1.y:(kk==2)?c1.z:c1.w;
            const int k = k4 * 4 + kk;
            const float4 wA = __ldg(wp + k * 16);
            const float4 wB = __ldg(wp + k * 16 + 1);
            FMA4(a0,       f0, wA);  FMA4((a0 + 4), f0, wB);
            FMA4(a1,       f1, wA);  FMA4((a1 + 4), f1, wB);
        }
        if (k4 < 15) { c0 = n0; c1 = n1; }
    }

    if (v0) {
        float4* op = (float4*)(out + (size_t)gr0 * F64) + o * 2;
        #pragma unroll
        for (int i = 0; i < 2; i++) {
            float4 v = make_float4(a0[4*i+0], a0[4*i+1], a0[4*i+2], a0[4*i+3]);
            if (do_relu) { v.x=fmaxf(v.x,0.f); v.y=fmaxf(v.y,0.f); v.z=fmaxf(v.z,0.f); v.w=fmaxf(v.w,0.f); }
            op[i] = v;
        }
    }
    if (v1) {
        float4* op = (float4*)(out + (size_t)gr1 * F64) + o * 2;
        #pragma unroll
        for (int i = 0; i < 2; i++) {
            float4 v = make_float4(a1[4*i+0], a1[4*i+1], a1[4*i+2], a1[4*i+3]);
            if (do_relu) { v.x=fmaxf(v.x,0.f); v.y=fmaxf(v.y,0.f); v.z=fmaxf(v.z,0.f); v.w=fmaxf(v.w,0.f); }
            op[i] = v;
        }
    }
}

// ---------------------------------------------------------------------------
// Fused MLP + head: out[row] = relu(in @ W2a + b2a) @ W2b + b2b (64 -> 1)
// Same L1-W tiling; 8-lane xor shfl-reduce epilogue.
// ---------------------------------------------------------------------------
__global__ void mlp_head_kernel(const float* __restrict__ in,
                                const float* __restrict__ Wa,
                                const float* __restrict__ ba,
                                const float* __restrict__ wv,
                                const float* __restrict__ bv,
                                float* __restrict__ out, int n)
{
    const int t  = threadIdx.x;
    const int o  = t & 7;
    const int rp = t >> 3;
    const int row_base = blockIdx.x * 64;
    int gr0 = row_base + rp;
    int gr1 = row_base + rp + 32;
    const bool v0 = (gr0 < n), v1 = (gr1 < n);
    if (!v0) gr0 = n - 1;
    if (!v1) gr1 = n - 1;

    const float4* x0p = (const float4*)(in + (size_t)gr0 * F64);
    const float4* x1p = (const float4*)(in + (size_t)gr1 * F64);
    const float4* wp  = (const float4*)(Wa + o * 8);

    float a0[8], a1[8];
    {
        const float4 bA = __ldg((const float4*)(ba + o * 8));
        const float4 bB = __ldg((const float4*)(ba + o * 8) + 1);
        a0[0]=bA.x; a0[1]=bA.y; a0[2]=bA.z; a0[3]=bA.w;
        a0[4]=bB.x; a0[5]=bB.y; a0[6]=bB.z; a0[7]=bB.w;
        #pragma unroll
        for (int j = 0; j < 8; j++) a1[j] = a0[j];
    }

    float4 c0 = __ldg(x0p);
    float4 c1 = __ldg(x1p);

    #pragma unroll
    for (int k4 = 0; k4 < 16; k4++) {
        float4 n0, n1;
        if (k4 < 15) {
            n0 = __ldg(x0p + k4 + 1);
            n1 = __ldg(x1p + k4 + 1);
        }
        #pragma unroll
        for (int kk = 0; kk < 4; kk++) {
            const float f0 = (kk==0)?c0.x:(kk==1)?c0.y:(kk==2)?c0.z:c0.w;
            const float f1 = (kk==0)?c1.x:(kk==1)?c1.y:(kk==2)?c1.z:c1.w;
            const int k = k4 * 4 + kk;
            const float4 wA = __ldg(wp + k * 16);
            const float4 wB = __ldg(wp + k * 16 + 1);
            FMA4(a0,       f0, wA);  FMA4((a0 + 4), f0, wB);
            FMA4(a1,       f1, wA);  FMA4((a1 + 4), f1, wB);
        }
        if (k4 < 15) { c0 = n0; c1 = n1; }
    }

    // head dot: cols [8o, 8o+8)
    const float4 hA = __ldg((const float4*)(wv + o * 8));
    const float4 hB = __ldg((const float4*)(wv + o * 8) + 1);
    float s0, s1;
    {
        float t0 = fmaxf(a0[0],0.f)*hA.x + fmaxf(a0[1],0.f)*hA.y
                 + fmaxf(a0[2],0.f)*hA.z + fmaxf(a0[3],0.f)*hA.w
                 + fmaxf(a0[4],0.f)*hB.x + fmaxf(a0[5],0.f)*hB.y
                 + fmaxf(a0[6],0.f)*hB.z + fmaxf(a0[7],0.f)*hB.w;
        float t1 = fmaxf(a1[0],0.f)*hA.x + fmaxf(a1[1],0.f)*hA.y
                 + fmaxf(a1[2],0.f)*hA.z + fmaxf(a1[3],0.f)*hA.w
                 + fmaxf(a1[4],0.f)*hB.x + fmaxf(a1[5],0.f)*hB.y
                 + fmaxf(a1[6],0.f)*hB.z + fmaxf(a1[7],0.f)*hB.w;
        s0 = t0; s1 = t1;
    }
    #pragma unroll
    for (int m = 1; m < 8; m <<= 1) {
        s0 += __shfl_xor_sync(0xffffffffu, s0, m, 32);
        s1 += __shfl_xor_sync(0xffffffffu, s1, m, 32);
    }

    if (o == 0) {
        const float bias = __ldg(bv);
        if (v0) out[gr0] = s0 + bias;
        if (v1) out[gr1] = s1 + bias;
    }
}

// ---------------------------------------------------------------------------
static inline int imin(int a, int b) { return a < b ? a : b; }

extern "C" void kernel_launch(void* const* d_in, const int* in_sizes, int n_in,
                              void* d_out, int out_size)
{
    const float* x_state   = (const float*)d_in[0];
    const float* x_task    = (const float*)d_in[1];
    const float* x_actor   = (const float*)d_in[2];
    const float* edge_attr = (const float*)d_in[3];
    const float* We  = (const float*)d_in[4];
    const float* be  = (const float*)d_in[5];
    const float* W1a = (const float*)d_in[6];
    const float* b1a = (const float*)d_in[7];
    const float* W1b = (const float*)d_in[8];
    const float* b1b = (const float*)d_in[9];
    const float* W2a = (const float*)d_in[10];
    const float* b2a = (const float*)d_in[11];
    const float* W2b = (const float*)d_in[12];
    const float* b2b = (const float*)d_in[13];
    const int* src_st = (const int*)d_in[14];
    const int* dst_st = (const int*)d_in[15];
    const int* src_ta = (const int*)d_in[16];
    const int* dst_ta = (const int*)d_in[17];

    const int n_task  = in_sizes[1] / F64;
    const int n_actor = in_sizes[2] / F64;
    const int E_st = in_sizes[14];
    const int E_ta = in_sizes[16];

    float *p_h_task, *p_tmp, *p_x1, *p_h2;
    cudaGetSymbolAddress((void**)&p_h_task, g_h_task);
    cudaGetSymbolAddress((void**)&p_tmp,    g_tmp);
    cudaGetSymbolAddress((void**)&p_x1,     g_x1);
    cudaGetSymbolAddress((void**)&p_h2,     g_h2);

    // 1) residual init
    init_kernel<<<1024, 256>>>(x_task, x_actor, n_task, n_actor);

    // 2) GINEConv message + scatter
    {
        int blocks = imin((E_st * 16 + 255) / 256, 148 * 48);
        edge_gine_kernel<<<blocks, 256>>>(x_state, edge_attr, We, be,
                                          src_st, dst_st, E_st);
    }

    // 3) task MLP: x1 = relu(h @ W1a + b1a) @ W1b + b1b
    {
        int gb = (n_task + 63) / 64;
        mlp_layer_kernel<<<gb, 256>>>(p_h_task, W1a, b1a, p_tmp, n_task, 1);
        mlp_layer_kernel<<<gb, 256>>>(p_tmp,    W1b, b1b, p_x1,  n_task, 0);
    }

    // 4) GINConv gather + scatter
    {
        int blocks = imin((E_ta * 16 + 255) / 256, 148 * 48);
        edge_gin_kernel<<<blocks, 256>>>(src_ta, dst_ta, E_ta);
    }

    // 5) actor MLP + head
    {
        int ga = (n_actor + 63) / 64;
        mlp_head_kernel<<<ga, 256>>>(p_h2, W2a, b2a, W2b, b2b, (float*)d_out, n_actor);
    }
}

// round 15
// speedup vs baseline: 1.1210x; 1.1210x over previous
#include <cuda_runtime.h>
#include <cstdint>

// ---------------------------------------------------------------------------
// CombinedGoalObsNetwork — R14: R11 edge kernels (LTS byte roofline, frozen)
// + TF32 tensor-core MLP (mma.sync.m16n8k8, tf32x3 split for fp32 accuracy).
// ---------------------------------------------------------------------------

#define F64 64
#define NTASK_MAX  32768
#define NACT_MAX   32768

__device__ __align__(16) float g_h_task[NTASK_MAX * F64];
__device__ __align__(16) float g_tmp   [NTASK_MAX * F64];
__device__ __align__(16) float g_x1    [NTASK_MAX * F64];
__device__ __align__(16) float g_h2    [NACT_MAX  * F64];

// ---------------------------------------------------------------------------
// Init: h_task = x_task ; h2 = x_actor
// ---------------------------------------------------------------------------
__global__ void init_kernel(const float* __restrict__ x_task,
                            const float* __restrict__ x_actor,
                            int n_task, int n_actor)
{
    int tot = gridDim.x * blockDim.x;
    int tid = blockIdx.x * blockDim.x + threadIdx.x;
    int nt4 = n_task * (F64 / 4);
    int na4 = n_actor * (F64 / 4);
    const float4* xt = (const float4*)x_task;
    const float4* xa = (const float4*)x_actor;
    float4* ht = (float4*)g_h_task;
    float4* h2 = (float4*)g_h2;
    for (int i = tid; i < nt4; i += tot) ht[i] = xt[i];
    for (int i = tid; i < na4; i += tot) h2[i] = xa[i];
}

__device__ __forceinline__ void red_add_v4(float* p, float4 v)
{
    asm volatile("red.global.add.v4.f32 [%0], {%1,%2,%3,%4};"
                 :: "l"(p), "f"(v.x), "f"(v.y), "f"(v.z), "f"(v.w)
                 : "memory");
}

// ---------------------------------------------------------------------------
// GINEConv edge kernel (frozen): 16 lanes/edge, float4 per lane.
// ---------------------------------------------------------------------------
__global__ void edge_gine_kernel(const float* __restrict__ x_state,
                                 const float* __restrict__ edge_attr,
                                 const float* __restrict__ We,
                                 const float* __restrict__ be,
                                 const int*   __restrict__ src,
                                 const int*   __restrict__ dst,
                                 int E)
{
    const int lane = threadIdx.x & 15;
    const float4 w0 = __ldg((const float4*)We + lane);
    const float4 w1 = __ldg((const float4*)(We + F64) + lane);
    const float4 bb = __ldg((const float4*)be + lane);

    int g  = (blockIdx.x * blockDim.x + threadIdx.x) >> 4;
    int gs = (gridDim.x * blockDim.x) >> 4;

    #pragma unroll 2
    for (int e = g; e < E; e += gs) {
        const int s = __ldg(src + e);
        const int d = __ldg(dst + e);
        const float2 a = __ldg((const float2*)edge_attr + e);
        const float4 x = __ldg((const float4*)(x_state + (size_t)s * F64) + lane);
        float4 v;
        v.x = fmaxf(fmaf(a.x, w0.x, fmaf(a.y, w1.x, x.x + bb.x)), 0.f);
        v.y = fmaxf(fmaf(a.x, w0.y, fmaf(a.y, w1.y, x.y + bb.y)), 0.f);
        v.z = fmaxf(fmaf(a.x, w0.z, fmaf(a.y, w1.z, x.z + bb.z)), 0.f);
        v.w = fmaxf(fmaf(a.x, w0.w, fmaf(a.y, w1.w, x.w + bb.w)), 0.f);
        red_add_v4(g_h_task + (size_t)d * F64 + lane * 4, v);
    }
}

// ---------------------------------------------------------------------------
// GINConv edge kernel (frozen): gather x1 row, scatter-add.
// ---------------------------------------------------------------------------
__global__ void edge_gin_kernel(const int* __restrict__ src,
                                const int* __restrict__ dst,
                                int E)
{
    const int lane = threadIdx.x & 15;
    int g  = (blockIdx.x * blockDim.x + threadIdx.x) >> 4;
    int gs = (gridDim.x * blockDim.x) >> 4;

    #pragma unroll 2
    for (int e = g; e < E; e += gs) {
        const int s = __ldg(src + e);
        const int d = __ldg(dst + e);
        const float4 v = *((const float4*)(g_x1 + (size_t)s * F64) + lane);
        red_add_v4(g_h2 + (size_t)d * F64 + lane * 4, v);
    }
}

// ---------------------------------------------------------------------------
// TF32 helpers
// ---------------------------------------------------------------------------
__device__ __forceinline__ uint32_t f2tf(float x)
{
    uint32_t r;
    asm("cvt.rna.tf32.f32 %0, %1;" : "=r"(r) : "f"(x));
    return r;
}

__device__ __forceinline__ void mma_tf32(float* c,
                                         uint32_t a0, uint32_t a1,
                                         uint32_t a2, uint32_t a3,
                                         uint32_t b0, uint32_t b1)
{
    asm volatile(
        "mma.sync.aligned.m16n8k8.row.col.f32.tf32.tf32.f32 "
        "{%0,%1,%2,%3}, {%4,%5,%6,%7}, {%8,%9}, {%0,%1,%2,%3};"
        : "+f"(c[0]), "+f"(c[1]), "+f"(c[2]), "+f"(c[3])
        : "r"(a0), "r"(a1), "r"(a2), "r"(a3), "r"(b0), "r"(b1));
}

// W staged as tf32 hi/lo at stride 72 words: addr mod 32 = 8*(k)+n%8 over the
// warp's (tg,gid) -> 32 distinct banks, conflict-free.
#define WP 72

// ---------------------------------------------------------------------------
// Dense 64x64 layer via tf32x3 mma. Block = 256 thr (8 warps) = 128 rows.
// Warp handles rows [rb, rb+16); 8 n-tiles of 8 cols; 8 k-steps of 8.
// D = Ahi*Bhi + Alo*Bhi + Ahi*Blo  (error ~2^-22, fp32-class).
// ---------------------------------------------------------------------------
__global__ void mlp_layer_tc(const float* __restrict__ in,
                             const float* __restrict__ W,
                             const float* __restrict__ b,
                             float* __restrict__ out,
                             int n, int do_relu)
{
    __shared__ uint32_t sWhi[64 * WP];
    __shared__ uint32_t sWlo[64 * WP];
    __shared__ float sb[F64];

    const int t = threadIdx.x;
    for (int i = t; i < 4096; i += 256) {
        const int k = i >> 6, nn = i & 63;
        const float w = __ldg(W + i);
        const uint32_t hi = f2tf(w);
        sWhi[k * WP + nn] = hi;
        sWlo[k * WP + nn] = f2tf(w - __uint_as_float(hi));
    }
    if (t < F64) sb[t] = b[t];
    __syncthreads();

    const int wid  = t >> 5;
    const int lane = t & 31;
    const int gid  = lane >> 2;      // 0..7
    const int tg   = lane & 3;       // 0..3
    const int rb   = blockIdx.x * 128 + wid * 16;
    const int r0   = rb + gid;
    const int r1   = rb + gid + 8;
    const bool v0 = (r0 < n), v1 = (r1 < n);
    const int cr0 = v0 ? r0 : (n - 1);
    const int cr1 = v1 ? r1 : (n - 1);

    const float* x0 = in + (size_t)cr0 * F64;
    const float* x1 = in + (size_t)cr1 * F64;

    float c[8][4];
    #pragma unroll
    for (int nt = 0; nt < 8; nt++) {
        c[nt][0] = 0.f; c[nt][1] = 0.f; c[nt][2] = 0.f; c[nt][3] = 0.f;
    }

    #pragma unroll
    for (int k0 = 0; k0 < 8; k0++) {
        const int kb = k0 * 8;
        const float f0 = __ldg(x0 + kb + tg);
        const float f1 = __ldg(x1 + kb + tg);
        const float f2 = __ldg(x0 + kb + tg + 4);
        const float f3 = __ldg(x1 + kb + tg + 4);
        const uint32_t ah0 = f2tf(f0), ah1 = f2tf(f1);
        const uint32_t ah2 = f2tf(f2), ah3 = f2tf(f3);
        const uint32_t al0 = f2tf(f0 - __uint_as_float(ah0));
        const uint32_t al1 = f2tf(f1 - __uint_as_float(ah1));
        const uint32_t al2 = f2tf(f2 - __uint_as_float(ah2));
        const uint32_t al3 = f2tf(f3 - __uint_as_float(ah3));

        const uint32_t* ph  = &sWhi[(kb + tg) * WP + gid];
        const uint32_t* ph4 = &sWhi[(kb + tg + 4) * WP + gid];
        const uint32_t* pl  = &sWlo[(kb + tg) * WP + gid];
        const uint32_t* pl4 = &sWlo[(kb + tg + 4) * WP + gid];

        #pragma unroll
        for (int nt = 0; nt < 8; nt++) {
            const uint32_t b0h = ph [nt * 8];
            const uint32_t b1h = ph4[nt * 8];
            const uint32_t b0l = pl [nt * 8];
            const uint32_t b1l = pl4[nt * 8];
            mma_tf32(c[nt], ah0, ah1, ah2, ah3, b0h, b1h);
            mma_tf32(c[nt], al0, al1, al2, al3, b0h, b1h);
            mma_tf32(c[nt], ah0, ah1, ah2, ah3, b0l, b1l);
        }
    }

    #pragma unroll
    for (int nt = 0; nt < 8; nt++) {
        const int col = nt * 8 + 2 * tg;
        float o0 = c[nt][0] + sb[col];
        float o1 = c[nt][1] + sb[col + 1];
        float o2 = c[nt][2] + sb[col];
        float o3 = c[nt][3] + sb[col + 1];
        if (do_relu) {
            o0 = fmaxf(o0, 0.f); o1 = fmaxf(o1, 0.f);
            o2 = fmaxf(o2, 0.f); o3 = fmaxf(o3, 0.f);
        }
        if (v0) *(float2*)(out + (size_t)r0 * F64 + col) = make_float2(o0, o1);
        if (v1) *(float2*)(out + (size_t)r1 * F64 + col) = make_float2(o2, o3);
    }
}

// ---------------------------------------------------------------------------
// Fused MLP + head via tf32x3 mma: out[row] = relu(in@Wa+ba) . wv + bv.
// Same tiling; epilogue dots with wv and reduces over the 4-lane group.
// ---------------------------------------------------------------------------
__global__ void mlp_head_tc(const float* __restrict__ in,
                            const float* __restrict__ Wa,
                            const float* __restrict__ ba,
                            const float* __restrict__ wv,
                            const float* __restrict__ bv,
                            float* __restrict__ out, int n)
{
    __shared__ uint32_t sWhi[64 * WP];
    __shared__ uint32_t sWlo[64 * WP];
    __shared__ float sb[F64];
    __shared__ float sw[F64];

    const int t = threadIdx.x;
    for (int i = t; i < 4096; i += 256) {
        const int k = i >> 6, nn = i & 63;
        const float w = __ldg(Wa + i);
        const uint32_t hi = f2tf(w);
        sWhi[k * WP + nn] = hi;
        sWlo[k * WP + nn] = f2tf(w - __uint_as_float(hi));
    }
    if (t < F64) { sb[t] = ba[t]; sw[t] = wv[t]; }
    __syncthreads();

    const int wid  = t >> 5;
    const int lane = t & 31;
    const int gid  = lane >> 2;
    const int tg   = lane & 3;
    const int rb   = blockIdx.x * 128 + wid * 16;
    const int r0   = rb + gid;
    const int r1   = rb + gid + 8;
    const bool v0 = (r0 < n), v1 = (r1 < n);
    const int cr0 = v0 ? r0 : (n - 1);
    const int cr1 = v1 ? r1 : (n - 1);

    const float* x0 = in + (size_t)cr0 * F64;
    const float* x1 = in + (size_t)cr1 * F64;

    float c[8][4];
    #pragma unroll
    for (int nt = 0; nt < 8; nt++) {
        c[nt][0] = 0.f; c[nt][1] = 0.f; c[nt][2] = 0.f; c[nt][3] = 0.f;
    }

    #pragma unroll
    for (int k0 = 0; k0 < 8; k0++) {
        const int kb = k0 * 8;
        const float f0 = __ldg(x0 + kb + tg);
        const float f1 = __ldg(x1 + kb + tg);
        const float f2 = __ldg(x0 + kb + tg + 4);
        const float f3 = __ldg(x1 + kb + tg + 4);
        const uint32_t ah0 = f2tf(f0), ah1 = f2tf(f1);
        const uint32_t ah2 = f2tf(f2), ah3 = f2tf(f3);
        const uint32_t al0 = f2tf(f0 - __uint_as_float(ah0));
        const uint32_t al1 = f2tf(f1 - __uint_as_float(ah1));
        const uint32_t al2 = f2tf(f2 - __uint_as_float(ah2));
        const uint32_t al3 = f2tf(f3 - __uint_as_float(ah3));

        const uint32_t* ph  = &sWhi[(kb + tg) * WP + gid];
        const uint32_t* ph4 = &sWhi[(kb + tg + 4) * WP + gid];
        const uint32_t* pl  = &sWlo[(kb + tg) * WP + gid];
        const uint32_t* pl4 = &sWlo[(kb + tg + 4) * WP + gid];

        #pragma unroll
        for (int nt = 0; nt < 8; nt++) {
            const uint32_t b0h = ph [nt * 8];
            const uint32_t b1h = ph4[nt * 8];
            const uint32_t b0l = pl [nt * 8];
            const uint32_t b1l = pl4[nt * 8];
            mma_tf32(c[nt], ah0, ah1, ah2, ah3, b0h, b1h);
            mma_tf32(c[nt], al0, al1, al2, al3, b0h, b1h);
            mma_tf32(c[nt], ah0, ah1, ah2, ah3, b0l, b1l);
        }
    }

    float s0 = 0.f, s1 = 0.f;
    #pragma unroll
    for (int nt = 0; nt < 8; nt++) {
        const int col = nt * 8 + 2 * tg;
        const float wv0 = sw[col], wv1 = sw[col + 1];
        s0 = fmaf(fmaxf(c[nt][0] + sb[col],     0.f), wv0, s0);
        s0 = fmaf(fmaxf(c[nt][1] + sb[col + 1], 0.f), wv1, s0);
        s1 = fmaf(fmaxf(c[nt][2] + sb[col],     0.f), wv0, s1);
        s1 = fmaf(fmaxf(c[nt][3] + sb[col + 1], 0.f), wv1, s1);
    }
    // reduce over the 4 lanes of the group (lanes differ in tg = low 2 bits)
    s0 += __shfl_xor_sync(0xffffffffu, s0, 1, 32);
    s0 += __shfl_xor_sync(0xffffffffu, s0, 2, 32);
    s1 += __shfl_xor_sync(0xffffffffu, s1, 1, 32);
    s1 += __shfl_xor_sync(0xffffffffu, s1, 2, 32);

    if (tg == 0) {
        const float bias = __ldg(bv);
        if (v0) out[r0] = s0 + bias;
        if (v1) out[r1] = s1 + bias;
    }
}

// ---------------------------------------------------------------------------
static inline int imin(int a, int b) { return a < b ? a : b; }

extern "C" void kernel_launch(void* const* d_in, const int* in_sizes, int n_in,
                              void* d_out, int out_size)
{
    const float* x_state   = (const float*)d_in[0];
    const float* x_task    = (const float*)d_in[1];
    const float* x_actor   = (const float*)d_in[2];
    const float* edge_attr = (const float*)d_in[3];
    const float* We  = (const float*)d_in[4];
    const float* be  = (const float*)d_in[5];
    const float* W1a = (const float*)d_in[6];
    const float* b1a = (const float*)d_in[7];
    const float* W1b = (const float*)d_in[8];
    const float* b1b = (const float*)d_in[9];
    const float* W2a = (const float*)d_in[10];
    const float* b2a = (const float*)d_in[11];
    const float* W2b = (const float*)d_in[12];
    const float* b2b = (const float*)d_in[13];
    const int* src_st = (const int*)d_in[14];
    const int* dst_st = (const int*)d_in[15];
    const int* src_ta = (const int*)d_in[16];
    const int* dst_ta = (const int*)d_in[17];

    const int n_task  = in_sizes[1] / F64;
    const int n_actor = in_sizes[2] / F64;
    const int E_st = in_sizes[14];
    const int E_ta = in_sizes[16];

    float *p_h_task, *p_tmp, *p_x1, *p_h2;
    cudaGetSymbolAddress((void**)&p_h_task, g_h_task);
    cudaGetSymbolAddress((void**)&p_tmp,    g_tmp);
    cudaGetSymbolAddress((void**)&p_x1,     g_x1);
    cudaGetSymbolAddress((void**)&p_h2,     g_h2);

    // 1) residual init
    init_kernel<<<1024, 256>>>(x_task, x_actor, n_task, n_actor);

    // 2) GINEConv message + scatter
    {
        int blocks = imin((E_st * 16 + 255) / 256, 148 * 48);
        edge_gine_kernel<<<blocks, 256>>>(x_state, edge_attr, We, be,
                                          src_st, dst_st, E_st);
    }

    // 3) task MLP via tensor cores
    {
        int gb = (n_task + 127) / 128;
        mlp_layer_tc<<<gb, 256>>>(p_h_task, W1a, b1a, p_tmp, n_task, 1);
        mlp_layer_tc<<<gb, 256>>>(p_tmp,    W1b, b1b, p_x1,  n_task, 0);
    }

    // 4) GINConv gather + scatter
    {
        int blocks = imin((E_ta * 16 + 255) / 256, 148 * 48);
        edge_gin_kernel<<<blocks, 256>>>(src_ta, dst_ta, E_ta);
    }

    // 5) actor MLP + head via tensor cores
    {
        int ga = (n_actor + 127) / 128;
        mlp_head_tc<<<ga, 256>>>(p_h2, W2a, b2a, W2b, b2b, (float*)d_out, n_actor);
    }
}